// round 13
// baseline (speedup 1.0000x reference)
#include <cuda_runtime.h>
#include <cuda_fp16.h>
#include <cstdint>

#define N_NODES 100000
#define N_EDGES 1600000
#define IN_DIM  32
#define HID     16
#define OUTD    8
#define CAP     64          // max tracked in-degree; P(Poisson(16) >= 64) ~ 1e-19
#define TB      256

// ---------------- device scratch (no allocation allowed) ----------------
// Invariants at entry to every kernel_launch (zero-init at load, restored
// at the end of each call): g_cnt == 0, g_bucketCnt == 0.
__device__ __half g_y1h[N_NODES * HID];  // x @ Wl1^T in fp16 (32B/row = 1 sector)
__device__ float  g_r1 [N_NODES * HID];  // x @ Wr1^T  (root term, fp32)
__device__ int    g_cnt[N_NODES];        // in-degree (ticket counter)
__device__ int    g_adj[(size_t)N_NODES * CAP]; // node-major: adj[dst*CAP + slot] = src
__device__ float  g_s2 [N_NODES];        // h @ (Wfc·Wl2)^T   (scalar per node)
__device__ float  g_r2s[N_NODES];        // h @ (Wfc·Wr2)^T   (scalar per node)
__device__ int    g_bucketCnt[CAP + 1];  // degree histogram
__device__ int    g_bucketOff[CAP + 1];  // exclusive offsets (mutated by place)
__device__ int    g_order[N_NODES];      // nodes sorted by degree

// ---------------- kernels ----------------

// per-node: y1h = fp16(x@Wl1^T), r1 = x@Wr1^T
__global__ void k_node1(const float* __restrict__ x,
                        const float* __restrict__ Wl1,
                        const float* __restrict__ Wr1) {
    __shared__ float sWl[HID * IN_DIM];
    __shared__ float sWr[HID * IN_DIM];
    for (int i = threadIdx.x; i < HID * IN_DIM; i += blockDim.x) {
        sWl[i] = Wl1[i];
        sWr[i] = Wr1[i];
    }
    __syncthreads();
    int n = blockIdx.x * blockDim.x + threadIdx.x;
    if (n >= N_NODES) return;

    float xv[IN_DIM];
    const float4* xr = reinterpret_cast<const float4*>(x + (size_t)n * IN_DIM);
#pragma unroll
    for (int i = 0; i < IN_DIM / 4; i++) {
        float4 v = xr[i];
        xv[4*i+0] = v.x; xv[4*i+1] = v.y; xv[4*i+2] = v.z; xv[4*i+3] = v.w;
    }
    float y[HID], r[HID];
#pragma unroll
    for (int c = 0; c < HID; c++) {
        float a = 0.f, b = 0.f;
#pragma unroll
        for (int k = 0; k < IN_DIM; k++) {
            a += xv[k] * sWl[c * IN_DIM + k];
            b += xv[k] * sWr[c * IN_DIM + k];
        }
        y[c] = a; r[c] = b;
    }
    uint32_t hp[8];
#pragma unroll
    for (int i = 0; i < 8; i++) {
        __half2 h = __floats2half2_rn(y[2*i], y[2*i+1]);
        hp[i] = *reinterpret_cast<uint32_t*>(&h);
    }
    uint4* yo = reinterpret_cast<uint4*>(g_y1h + (size_t)n * HID);
    yo[0] = make_uint4(hp[0], hp[1], hp[2], hp[3]);
    yo[1] = make_uint4(hp[4], hp[5], hp[6], hp[7]);

    float4* ro = reinterpret_cast<float4*>(g_r1 + (size_t)n * HID);
#pragma unroll
    for (int i = 0; i < HID / 4; i++)
        ro[i] = make_float4(r[4*i], r[4*i+1], r[4*i+2], r[4*i+3]);
}

// build padded node-major adjacency: one pass, 4 edges per thread
__global__ void k_build(const int* __restrict__ ei) {
    int e4 = blockIdx.x * blockDim.x + threadIdx.x;
    if (e4 >= N_EDGES / 4) return;
    int4 s4 = reinterpret_cast<const int4*>(ei)[e4];
    int4 d4 = reinterpret_cast<const int4*>(ei + N_EDGES)[e4];
    int ss[4] = { s4.x, s4.y, s4.z, s4.w };
    int dd[4] = { d4.x, d4.y, d4.z, d4.w };
#pragma unroll
    for (int j = 0; j < 4; j++) {
        int slot = atomicAdd(&g_cnt[dd[j]], 1);
        if (slot < CAP)
            g_adj[(size_t)dd[j] * CAP + slot] = ss[j];
    }
}

// degree histogram, smem-privatized
__global__ void k_hist() {
    __shared__ int sh[CAP + 1];
    int t = threadIdx.x;
    if (t <= CAP) sh[t] = 0;
    __syncthreads();
    int n = blockIdx.x * blockDim.x + t;
    if (n < N_NODES) {
        int d = g_cnt[n];
        if (d > CAP) d = CAP;
        atomicAdd(&sh[d], 1);
    }
    __syncthreads();
    if (t <= CAP && sh[t])
        atomicAdd(&g_bucketCnt[t], sh[t]);
}

// exclusive scan of the 65-entry histogram; re-zero histogram for next launch
__global__ void k_scan() {
    __shared__ int s[CAP + 1];
    int t = threadIdx.x;                 // 128 threads
    if (t <= CAP) s[t] = g_bucketCnt[t];
    __syncthreads();
    for (int off = 1; off <= CAP; off <<= 1) {
        int v = 0;
        if (t <= CAP && t >= off) v = s[t - off];
        __syncthreads();
        if (t <= CAP) s[t] += v;
        __syncthreads();
    }
    if (t <= CAP) {
        g_bucketOff[t] = s[t] - g_bucketCnt[t];   // exclusive
        g_bucketCnt[t] = 0;                       // restore invariant
    }
}

// place nodes into degree-sorted order (block-privatized chunk allocation)
__global__ void k_place() {
    __shared__ int shCnt[CAP + 1];
    __shared__ int shBase[CAP + 1];
    int t = threadIdx.x;
    if (t <= CAP) shCnt[t] = 0;
    __syncthreads();
    int n = blockIdx.x * blockDim.x + t;
    int b = 0, rank = 0;
    if (n < N_NODES) {
        int d = g_cnt[n];
        b = d > CAP ? CAP : d;
        rank = atomicAdd(&shCnt[b], 1);
    }
    __syncthreads();
    if (t <= CAP && shCnt[t])
        shBase[t] = atomicAdd(&g_bucketOff[t], shCnt[t]);
    __syncthreads();
    if (n < N_NODES)
        g_order[shBase[b] + rank] = n;
}

// load 16B (8 halfs) of neighbor s's y1h row, half `sub` of the row
__device__ __forceinline__ uint4 ld_y1h(int s, int sub) {
    return reinterpret_cast<const uint4*>(g_y1h + (size_t)s * HID)[sub];
}
__device__ __forceinline__ void acc_h8(float* acc, uint4 v) {
    const uint32_t u[4] = { v.x, v.y, v.z, v.w };
#pragma unroll
    for (int i = 0; i < 4; i++) {
        __half2 h = *reinterpret_cast<const __half2*>(&u[i]);
        float2 f = __half22float2(h);
        acc[2*i+0] += f.x;
        acc[2*i+1] += f.y;
    }
}

// fused: layer-1 mean-aggregate (fp16 cooperative gather, 2 lanes/node,
// degree-sorted node order -> warp-uniform loop counts) + relu + layer-2
// projections collapsed to scalars through Wfc.
__global__ void k_agg1(const float* __restrict__ Wl2,
                       const float* __restrict__ Wr2,
                       const float* __restrict__ Wfc,
                       const float* __restrict__ bl1) {
    __shared__ float sW2fc[HID];    // Wfc @ Wl2   (1x16)
    __shared__ float sWr2fc[HID];   // Wfc @ Wr2   (1x16)
    __shared__ float sbl1[HID];
    int t = threadIdx.x;
    if (t < HID) {
        float a = 0.f;
#pragma unroll
        for (int o = 0; o < OUTD; o++) a += Wfc[o] * Wl2[o * HID + t];
        sW2fc[t] = a;
    } else if (t < 2 * HID) {
        int j = t - HID;
        float a = 0.f;
#pragma unroll
        for (int o = 0; o < OUTD; o++) a += Wfc[o] * Wr2[o * HID + j];
        sWr2fc[j] = a;
    } else if (t < 3 * HID) {
        sbl1[t - 2 * HID] = bl1[t - 2 * HID];
    }
    __syncthreads();

    int g   = blockIdx.x * (blockDim.x / 2) + (t >> 1);
    int sub = t & 1;
    bool valid = g < N_NODES;
    int gi = valid ? g : (N_NODES - 1);
    int node = g_order[gi];

    int degFull = g_cnt[node];
    int deg = degFull < CAP ? degFull : CAP;
    if (!valid) deg = 0;

    const int* arow = g_adj + (size_t)node * CAP;

    float acc[8] = {0.f,0.f,0.f,0.f,0.f,0.f,0.f,0.f};
    int i = 0;
    for (; i + 8 <= deg; i += 8) {
        int4 ia = *reinterpret_cast<const int4*>(arow + i);
        int4 ib = *reinterpret_cast<const int4*>(arow + i + 4);
        uint4 v0 = ld_y1h(ia.x, sub);
        uint4 v1 = ld_y1h(ia.y, sub);
        uint4 v2 = ld_y1h(ia.z, sub);
        uint4 v3 = ld_y1h(ia.w, sub);
        uint4 v4 = ld_y1h(ib.x, sub);
        uint4 v5 = ld_y1h(ib.y, sub);
        uint4 v6 = ld_y1h(ib.z, sub);
        uint4 v7 = ld_y1h(ib.w, sub);
        acc_h8(acc, v0); acc_h8(acc, v1); acc_h8(acc, v2); acc_h8(acc, v3);
        acc_h8(acc, v4); acc_h8(acc, v5); acc_h8(acc, v6); acc_h8(acc, v7);
    }
    if (i + 4 <= deg) {
        int4 ia = *reinterpret_cast<const int4*>(arow + i);
        uint4 v0 = ld_y1h(ia.x, sub);
        uint4 v1 = ld_y1h(ia.y, sub);
        uint4 v2 = ld_y1h(ia.z, sub);
        uint4 v3 = ld_y1h(ia.w, sub);
        acc_h8(acc, v0); acc_h8(acc, v1); acc_h8(acc, v2); acc_h8(acc, v3);
        i += 4;
    }
    for (; i < deg; i++) {
        acc_h8(acc, ld_y1h(arow[i], sub));
    }

    float inv = 1.0f / fmaxf((float)degFull, 1.0f);
    const float4* rr = reinterpret_cast<const float4*>(g_r1 + (size_t)node * HID);
    float4 r0 = rr[2*sub + 0];
    float4 r1 = rr[2*sub + 1];
    const float4* bb = reinterpret_cast<const float4*>(sbl1);
    float4 b0 = bb[2*sub + 0], b1 = bb[2*sub + 1];
    const float4* wlp = reinterpret_cast<const float4*>(sW2fc);
    float4 wl0 = wlp[2*sub + 0], wl1 = wlp[2*sub + 1];
    const float4* wrp = reinterpret_cast<const float4*>(sWr2fc);
    float4 wr0 = wrp[2*sub + 0], wr1 = wrp[2*sub + 1];

    float rv[8] = { r0.x,r0.y,r0.z,r0.w, r1.x,r1.y,r1.z,r1.w };
    float bv[8] = { b0.x,b0.y,b0.z,b0.w, b1.x,b1.y,b1.z,b1.w };
    float wlv[8]= { wl0.x,wl0.y,wl0.z,wl0.w, wl1.x,wl1.y,wl1.z,wl1.w };
    float wrv[8]= { wr0.x,wr0.y,wr0.z,wr0.w, wr1.x,wr1.y,wr1.z,wr1.w };

    float s2p = 0.f, r2p = 0.f;
#pragma unroll
    for (int k = 0; k < 8; k++) {
        float h = fmaxf(acc[k] * inv + bv[k] + rv[k], 0.f);
        s2p += h * wlv[k];
        r2p += h * wrv[k];
    }
    s2p += __shfl_xor_sync(0xFFFFFFFFu, s2p, 1);
    r2p += __shfl_xor_sync(0xFFFFFFFFu, r2p, 1);

    if (valid && sub == 0) {
        g_s2[node]  = s2p;
        g_r2s[node] = r2p;
    }
}

// fused: layer-2 scalar mean-aggregate + final head (degree-sorted order).
// 4 lanes per node. Restores g_cnt == 0 for the next launch.
__global__ void k_agg2(const float* __restrict__ bl2,
                       const float* __restrict__ Wfc,
                       const float* __restrict__ bfc,
                       float* __restrict__ out) {
    __shared__ float sc;   // dot(Wfc, bl2) + bfc
    if (threadIdx.x == 0) {
        float c = bfc[0];
#pragma unroll
        for (int o = 0; o < OUTD; o++) c += Wfc[o] * bl2[o];
        sc = c;
    }
    __syncthreads();

    int t = threadIdx.x;
    int g   = blockIdx.x * (blockDim.x / 4) + (t >> 2);
    int sub = t & 3;
    bool valid = g < N_NODES;
    int gi = valid ? g : (N_NODES - 1);
    int node = g_order[gi];

    int degFull = g_cnt[node];
    int deg = degFull < CAP ? degFull : CAP;
    if (!valid) deg = 0;

    const int* arow = g_adj + (size_t)node * CAP;

    float s = 0.f;
    for (int base = 4 * sub; base < deg; base += 16) {
        int4 ia = *reinterpret_cast<const int4*>(arow + base);
        if (base + 0 < deg) s += g_s2[ia.x];
        if (base + 1 < deg) s += g_s2[ia.y];
        if (base + 2 < deg) s += g_s2[ia.z];
        if (base + 3 < deg) s += g_s2[ia.w];
    }
    s += __shfl_xor_sync(0xFFFFFFFFu, s, 1);
    s += __shfl_xor_sync(0xFFFFFFFFu, s, 2);

    if (valid && sub == 0) {
        float inv = 1.0f / fmaxf((float)degFull, 1.0f);
        out[node] = s * inv + sc + g_r2s[node];
        g_cnt[node] = 0;   // restore invariant for the next launch
    }
}

// ---------------- launch ----------------
extern "C" void kernel_launch(void* const* d_in, const int* in_sizes, int n_in,
                              void* d_out, int out_size) {
    const float* x   = (const float*)d_in[0];
    const int*   ei  = (const int*)  d_in[1];
    const float* Wl1 = (const float*)d_in[2];
    const float* bl1 = (const float*)d_in[3];
    const float* Wr1 = (const float*)d_in[4];
    const float* Wl2 = (const float*)d_in[5];
    const float* bl2 = (const float*)d_in[6];
    const float* Wr2 = (const float*)d_in[7];
    const float* Wfc = (const float*)d_in[8];
    const float* bfc = (const float*)d_in[9];
    float* out = (float*)d_out;

    const int nodeBlocks = (N_NODES + TB - 1) / TB;          // 391
    const int edgeBlocks = (N_EDGES / 4 + TB - 1) / TB;      // 1563

    k_node1<<<nodeBlocks, TB>>>(x, Wl1, Wr1);
    k_build<<<edgeBlocks, TB>>>(ei);
    k_hist <<<nodeBlocks, TB>>>();
    k_scan <<<1, 128>>>();
    k_place<<<nodeBlocks, TB>>>();
    const int grp2 = (N_NODES + (TB / 2) - 1) / (TB / 2);    // 2 lanes per node
    k_agg1 <<<grp2, TB>>>(Wl2, Wr2, Wfc, bl1);
    const int grp4 = (N_NODES + (TB / 4) - 1) / (TB / 4);    // 4 lanes per node
    k_agg2 <<<grp4, TB>>>(bl2, Wfc, bfc, out);
}

// round 14
// speedup vs baseline: 1.1201x; 1.1201x over previous
#include <cuda_runtime.h>
#include <cuda_fp16.h>
#include <cstdint>

#define N_NODES 100000
#define N_EDGES 1600000
#define IN_DIM  32
#define HID     16
#define OUTD    8
#define CAP     64          // max tracked in-degree; P(Poisson(16) >= 64) ~ 1e-19
#define TB      256

// ---------------- device scratch (no allocation allowed) ----------------
// g_cnt invariant: zero at entry to every kernel_launch call (zero-initialized
// at module load; k_agg2 re-zeroes it after consuming the degrees).
__device__ __half g_y1h[N_NODES * HID];  // x @ Wl1^T in fp16 (32B/row = 1 sector)
__device__ float  g_r1 [N_NODES * HID];  // x @ Wr1^T  (root term, fp32)
__device__ int    g_cnt[N_NODES];        // in-degree (ticket counter)
__device__ int    g_adj[(size_t)N_NODES * CAP]; // node-major: adj[dst*CAP + slot] = src
__device__ float  g_s2 [N_NODES];        // h @ (Wfc·Wl2)^T   (scalar per node)
__device__ float  g_r2s[N_NODES];        // h @ (Wfc·Wr2)^T   (scalar per node)

// ---------------- host-side stream/event singletons (created once, pre-main;
// no device memory involved) ----------------
struct GraphForkResources {
    cudaStream_t s1;
    cudaEvent_t  evFork, evJoin;
    GraphForkResources() {
        cudaStreamCreateWithFlags(&s1, cudaStreamNonBlocking);
        cudaEventCreateWithFlags(&evFork, cudaEventDisableTiming);
        cudaEventCreateWithFlags(&evJoin, cudaEventDisableTiming);
    }
};
static GraphForkResources g_fork;

// ---------------- kernels ----------------

// build padded node-major adjacency: one pass, 4 edges per thread.
// Relies on g_cnt == 0 at entry (restored by k_agg2 of the previous call).
__global__ void k_build(const int* __restrict__ ei) {
    int e4 = blockIdx.x * blockDim.x + threadIdx.x;
    if (e4 >= N_EDGES / 4) return;
    int4 s4 = __ldg(reinterpret_cast<const int4*>(ei) + e4);
    int4 d4 = __ldg(reinterpret_cast<const int4*>(ei + N_EDGES) + e4);
    int ss[4] = { s4.x, s4.y, s4.z, s4.w };
    int dd[4] = { d4.x, d4.y, d4.z, d4.w };
#pragma unroll
    for (int j = 0; j < 4; j++) {
        int slot = atomicAdd(&g_cnt[dd[j]], 1);
        if (slot < CAP)
            g_adj[(size_t)dd[j] * CAP + slot] = ss[j];
    }
}

// per-node: y1h = fp16(x@Wl1^T), r1 = x@Wr1^T.  (Does NOT touch g_cnt: runs
// concurrently with k_build in the captured graph.)
__global__ void k_node1(const float* __restrict__ x,
                        const float* __restrict__ Wl1,
                        const float* __restrict__ Wr1) {
    __shared__ float sWl[HID * IN_DIM];
    __shared__ float sWr[HID * IN_DIM];
    for (int i = threadIdx.x; i < HID * IN_DIM; i += blockDim.x) {
        sWl[i] = Wl1[i];
        sWr[i] = Wr1[i];
    }
    __syncthreads();
    int n = blockIdx.x * blockDim.x + threadIdx.x;
    if (n >= N_NODES) return;

    float xv[IN_DIM];
    const float4* xr = reinterpret_cast<const float4*>(x + (size_t)n * IN_DIM);
#pragma unroll
    for (int i = 0; i < IN_DIM / 4; i++) {
        float4 v = xr[i];
        xv[4*i+0] = v.x; xv[4*i+1] = v.y; xv[4*i+2] = v.z; xv[4*i+3] = v.w;
    }
    float y[HID], r[HID];
#pragma unroll
    for (int c = 0; c < HID; c++) {
        float a = 0.f, b = 0.f;
#pragma unroll
        for (int k = 0; k < IN_DIM; k++) {
            a += xv[k] * sWl[c * IN_DIM + k];
            b += xv[k] * sWr[c * IN_DIM + k];
        }
        y[c] = a; r[c] = b;
    }
    uint32_t hp[8];
#pragma unroll
    for (int i = 0; i < 8; i++) {
        __half2 h = __floats2half2_rn(y[2*i], y[2*i+1]);
        hp[i] = *reinterpret_cast<uint32_t*>(&h);
    }
    uint4* yo = reinterpret_cast<uint4*>(g_y1h + (size_t)n * HID);
    yo[0] = make_uint4(hp[0], hp[1], hp[2], hp[3]);
    yo[1] = make_uint4(hp[4], hp[5], hp[6], hp[7]);

    float4* ro = reinterpret_cast<float4*>(g_r1 + (size_t)n * HID);
#pragma unroll
    for (int i = 0; i < HID / 4; i++)
        ro[i] = make_float4(r[4*i], r[4*i+1], r[4*i+2], r[4*i+3]);
}

// load 16B (8 halfs) of neighbor s's y1h row, half `sub` of the row
__device__ __forceinline__ uint4 ld_y1h(int s, int sub) {
    return __ldg(reinterpret_cast<const uint4*>(g_y1h + (size_t)s * HID) + sub);
}
__device__ __forceinline__ void acc_h8(float* acc, uint4 v) {
    const uint32_t u[4] = { v.x, v.y, v.z, v.w };
#pragma unroll
    for (int i = 0; i < 4; i++) {
        __half2 h = *reinterpret_cast<const __half2*>(&u[i]);
        float2 f = __half22float2(h);
        acc[2*i+0] += f.x;
        acc[2*i+1] += f.y;
    }
}

// fused: layer-1 mean-aggregate (fp16 cooperative gather, 2 lanes/node)
// + relu + layer-2 projections collapsed to scalars through Wfc.
// lane `sub` owns dims [8*sub, 8*sub+8).
__global__ void k_agg1(const float* __restrict__ Wl2,
                       const float* __restrict__ Wr2,
                       const float* __restrict__ Wfc,
                       const float* __restrict__ bl1) {
    __shared__ float sW2fc[HID];    // Wfc @ Wl2   (1x16)
    __shared__ float sWr2fc[HID];   // Wfc @ Wr2   (1x16)
    __shared__ float sbl1[HID];
    int t = threadIdx.x;
    if (t < HID) {
        float a = 0.f;
#pragma unroll
        for (int o = 0; o < OUTD; o++) a += Wfc[o] * Wl2[o * HID + t];
        sW2fc[t] = a;
    } else if (t < 2 * HID) {
        int j = t - HID;
        float a = 0.f;
#pragma unroll
        for (int o = 0; o < OUTD; o++) a += Wfc[o] * Wr2[o * HID + j];
        sWr2fc[j] = a;
    } else if (t < 3 * HID) {
        sbl1[t - 2 * HID] = bl1[t - 2 * HID];
    }
    __syncthreads();

    int node = blockIdx.x * (blockDim.x / 2) + (t >> 1);
    int sub  = t & 1;
    bool valid = node < N_NODES;
    int nC = valid ? node : (N_NODES - 1);

    int degFull = valid ? g_cnt[nC] : 0;
    int deg = degFull < CAP ? degFull : CAP;

    const int* arow = g_adj + (size_t)nC * CAP;

    float acc[8] = {0.f,0.f,0.f,0.f,0.f,0.f,0.f,0.f};
    int i = 0;
    // 8-wide batches: 2 int4 index loads + 8 independent 16B gathers in flight
    for (; i + 8 <= deg; i += 8) {
        int4 ia = __ldg(reinterpret_cast<const int4*>(arow + i));
        int4 ib = __ldg(reinterpret_cast<const int4*>(arow + i + 4));
        uint4 v0 = ld_y1h(ia.x, sub);
        uint4 v1 = ld_y1h(ia.y, sub);
        uint4 v2 = ld_y1h(ia.z, sub);
        uint4 v3 = ld_y1h(ia.w, sub);
        uint4 v4 = ld_y1h(ib.x, sub);
        uint4 v5 = ld_y1h(ib.y, sub);
        uint4 v6 = ld_y1h(ib.z, sub);
        uint4 v7 = ld_y1h(ib.w, sub);
        acc_h8(acc, v0); acc_h8(acc, v1); acc_h8(acc, v2); acc_h8(acc, v3);
        acc_h8(acc, v4); acc_h8(acc, v5); acc_h8(acc, v6); acc_h8(acc, v7);
    }
    if (i + 4 <= deg) {
        int4 ia = __ldg(reinterpret_cast<const int4*>(arow + i));
        uint4 v0 = ld_y1h(ia.x, sub);
        uint4 v1 = ld_y1h(ia.y, sub);
        uint4 v2 = ld_y1h(ia.z, sub);
        uint4 v3 = ld_y1h(ia.w, sub);
        acc_h8(acc, v0); acc_h8(acc, v1); acc_h8(acc, v2); acc_h8(acc, v3);
        i += 4;
    }
    for (; i < deg; i++) {
        acc_h8(acc, ld_y1h(arow[i], sub));
    }

    // per-lane epilogue on its own 8 dims
    float inv = 1.0f / fmaxf((float)degFull, 1.0f);
    const float4* rr = reinterpret_cast<const float4*>(g_r1 + (size_t)nC * HID);
    float4 r0 = rr[2*sub + 0];
    float4 r1 = rr[2*sub + 1];
    const float4* bb = reinterpret_cast<const float4*>(sbl1);
    float4 b0 = bb[2*sub + 0], b1 = bb[2*sub + 1];
    const float4* wlp = reinterpret_cast<const float4*>(sW2fc);
    float4 wl0 = wlp[2*sub + 0], wl1 = wlp[2*sub + 1];
    const float4* wrp = reinterpret_cast<const float4*>(sWr2fc);
    float4 wr0 = wrp[2*sub + 0], wr1 = wrp[2*sub + 1];

    float rv[8] = { r0.x,r0.y,r0.z,r0.w, r1.x,r1.y,r1.z,r1.w };
    float bv[8] = { b0.x,b0.y,b0.z,b0.w, b1.x,b1.y,b1.z,b1.w };
    float wlv[8]= { wl0.x,wl0.y,wl0.z,wl0.w, wl1.x,wl1.y,wl1.z,wl1.w };
    float wrv[8]= { wr0.x,wr0.y,wr0.z,wr0.w, wr1.x,wr1.y,wr1.z,wr1.w };

    float s2p = 0.f, r2p = 0.f;
#pragma unroll
    for (int k = 0; k < 8; k++) {
        float h = fmaxf(acc[k] * inv + bv[k] + rv[k], 0.f);
        s2p += h * wlv[k];
        r2p += h * wrv[k];
    }
    s2p += __shfl_xor_sync(0xFFFFFFFFu, s2p, 1);
    r2p += __shfl_xor_sync(0xFFFFFFFFu, r2p, 1);

    if (valid && sub == 0) {
        g_s2[node]  = s2p;
        g_r2s[node] = r2p;
    }
}

// fused: layer-2 scalar mean-aggregate + final head.
// 4 lanes per node; lane `sub` owns contiguous index chunks via int4.
// Restores the g_cnt == 0 invariant for the next launch.
__global__ void k_agg2(const float* __restrict__ bl2,
                       const float* __restrict__ Wfc,
                       const float* __restrict__ bfc,
                       float* __restrict__ out) {
    __shared__ float sc;   // dot(Wfc, bl2) + bfc
    if (threadIdx.x == 0) {
        float c = bfc[0];
#pragma unroll
        for (int o = 0; o < OUTD; o++) c += Wfc[o] * bl2[o];
        sc = c;
    }
    __syncthreads();

    int t = threadIdx.x;
    int node = blockIdx.x * (blockDim.x / 4) + (t >> 2);
    int sub  = t & 3;
    bool valid = node < N_NODES;
    int nC = valid ? node : (N_NODES - 1);

    int degFull = valid ? g_cnt[nC] : 0;
    int deg = degFull < CAP ? degFull : CAP;

    const int* arow = g_adj + (size_t)nC * CAP;

    float s = 0.f;
    for (int base = 4 * sub; base < deg; base += 16) {
        int4 ia = __ldg(reinterpret_cast<const int4*>(arow + base));
        if (base + 0 < deg) s += __ldg(&g_s2[ia.x]);
        if (base + 1 < deg) s += __ldg(&g_s2[ia.y]);
        if (base + 2 < deg) s += __ldg(&g_s2[ia.z]);
        if (base + 3 < deg) s += __ldg(&g_s2[ia.w]);
    }
    s += __shfl_xor_sync(0xFFFFFFFFu, s, 1);
    s += __shfl_xor_sync(0xFFFFFFFFu, s, 2);

    if (valid && sub == 0) {
        float inv = 1.0f / fmaxf((float)degFull, 1.0f);
        out[node] = s * inv + sc + g_r2s[node];
        g_cnt[node] = 0;   // restore invariant for the next launch
    }
}

// ---------------- launch ----------------
extern "C" void kernel_launch(void* const* d_in, const int* in_sizes, int n_in,
                              void* d_out, int out_size) {
    const float* x   = (const float*)d_in[0];
    const int*   ei  = (const int*)  d_in[1];
    const float* Wl1 = (const float*)d_in[2];
    const float* bl1 = (const float*)d_in[3];
    const float* Wr1 = (const float*)d_in[4];
    const float* Wl2 = (const float*)d_in[5];
    const float* bl2 = (const float*)d_in[6];
    const float* Wr2 = (const float*)d_in[7];
    const float* Wfc = (const float*)d_in[8];
    const float* bfc = (const float*)d_in[9];
    float* out = (float*)d_out;

    const int nodeBlocks = (N_NODES + TB - 1) / TB;          // 391
    const int edgeBlocks = (N_EDGES / 4 + TB - 1) / TB;      // 1563

    // Fork: run k_build (stream s1) concurrently with k_node1 (main stream).
    // They touch disjoint state (adj/cnt vs y1h/r1). Join before k_agg1.
    cudaEventRecord(g_fork.evFork, 0);
    cudaStreamWaitEvent(g_fork.s1, g_fork.evFork, 0);
    k_build<<<edgeBlocks, TB, 0, g_fork.s1>>>(ei);
    k_node1<<<nodeBlocks, TB>>>(x, Wl1, Wr1);
    cudaEventRecord(g_fork.evJoin, g_fork.s1);
    cudaStreamWaitEvent(0, g_fork.evJoin, 0);

    const int grp2 = (N_NODES + (TB / 2) - 1) / (TB / 2);    // 2 lanes per node
    k_agg1 <<<grp2, TB>>>(Wl2, Wr2, Wfc, bl1);
    const int grp4 = (N_NODES + (TB / 4) - 1) / (TB / 4);    // 4 lanes per node
    k_agg2 <<<grp4, TB>>>(bl2, Wfc, bfc, out);
}

// round 15
// speedup vs baseline: 1.1489x; 1.0257x over previous
#include <cuda_runtime.h>
#include <cuda_fp16.h>
#include <cstdint>

#define N_NODES 100000
#define N_EDGES 1600000
#define IN_DIM  32
#define HID     16
#define OUTD    8
#define CAP     64          // max tracked in-degree; P(Poisson(16) >= 64) ~ 1e-19
#define TB      256

// ---------------- device scratch (no allocation allowed) ----------------
// g_cnt invariant: zero at entry (zero-init at load; phase C re-zeroes it).
// Barrier state: sense-reversing, returns to initial state after the 2
// barriers of each launch.
__device__ __half g_y1h[N_NODES * HID];  // x @ Wl1^T in fp16 (32B/row = 1 sector)
__device__ float  g_r1 [N_NODES * HID];  // x @ Wr1^T  (root term, fp32)
__device__ int    g_cnt[N_NODES];        // in-degree (ticket counter)
__device__ int    g_adj[(size_t)N_NODES * CAP]; // node-major: adj[dst*CAP + slot] = src
__device__ float  g_s2 [N_NODES];        // h @ (Wfc·Wl2)^T   (scalar per node)
__device__ float  g_r2s[N_NODES];        // h @ (Wfc·Wr2)^T   (scalar per node)
__device__ int           g_barCnt = 0;
__device__ volatile int  g_barSense = 0;

// software grid barrier: grid is sized <= maxActiveBlocks*SMs, so every block
// is resident and the spin cannot deadlock.
__device__ __forceinline__ void gridBarrier(int& localSense) {
    __threadfence();          // publish this thread's writes
    __syncthreads();
    if (threadIdx.x == 0) {
        int s = localSense ^ 1;
        localSense = s;
        int arrived = atomicAdd(&g_barCnt, 1) + 1;
        if (arrived == (int)gridDim.x) {
            g_barCnt = 0;
            __threadfence();
            g_barSense = s;   // release
        } else {
            while (g_barSense != s) { }
        }
    }
    __syncthreads();
}

// load 16B (8 halfs) of neighbor s's y1h row, half `sub` of the row
__device__ __forceinline__ uint4 ld_y1h(int s, int sub) {
    return __ldg(reinterpret_cast<const uint4*>(g_y1h + (size_t)s * HID) + sub);
}
__device__ __forceinline__ void acc_h8(float* acc, uint4 v) {
    const uint32_t u[4] = { v.x, v.y, v.z, v.w };
#pragma unroll
    for (int i = 0; i < 4; i++) {
        __half2 h = *reinterpret_cast<const __half2*>(&u[i]);
        float2 f = __half22float2(h);
        acc[2*i+0] += f.x;
        acc[2*i+1] += f.y;
    }
}

// ---------------- the whole network in one persistent kernel ----------------
__global__ void __launch_bounds__(TB, 4)
k_fused(const float* __restrict__ x,
        const int*   __restrict__ ei,
        const float* __restrict__ Wl1,
        const float* __restrict__ Wr1,
        const float* __restrict__ Wl2,
        const float* __restrict__ Wr2,
        const float* __restrict__ Wfc,
        const float* __restrict__ bl1,
        const float* __restrict__ bl2,
        const float* __restrict__ bfc,
        float* __restrict__ out) {
    __shared__ float sWl[HID * IN_DIM];
    __shared__ float sWr[HID * IN_DIM];
    __shared__ float sW2fc[HID];    // Wfc @ Wl2
    __shared__ float sWr2fc[HID];   // Wfc @ Wr2
    __shared__ float sbl1[HID];
    __shared__ float sc[1];         // dot(Wfc, bl2) + bfc

    int t = threadIdx.x;
    int localSense = 0;

    for (int i = t; i < HID * IN_DIM; i += TB) {
        sWl[i] = Wl1[i];
        sWr[i] = Wr1[i];
    }
    if (t < HID) {
        float a = 0.f, b = 0.f;
#pragma unroll
        for (int o = 0; o < OUTD; o++) {
            a += Wfc[o] * Wl2[o * HID + t];
            b += Wfc[o] * Wr2[o * HID + t];
        }
        sW2fc[t]  = a;
        sWr2fc[t] = b;
        sbl1[t]   = bl1[t];
    }
    if (t == 0) {
        float c = bfc[0];
#pragma unroll
        for (int o = 0; o < OUTD; o++) c += Wfc[o] * bl2[o];
        sc[0] = c;
    }
    __syncthreads();

    // ---------------- Phase A: adjacency build + node MLP ----------------
    // Grid-stride loops; blocks that finish the edge range early move on to
    // the MLP range, so both workloads co-run across the resident grid.
    const int gridThreads = gridDim.x * TB;
    for (int e4 = blockIdx.x * TB + t; e4 < N_EDGES / 4; e4 += gridThreads) {
        int4 s4 = __ldg(reinterpret_cast<const int4*>(ei) + e4);
        int4 d4 = __ldg(reinterpret_cast<const int4*>(ei + N_EDGES) + e4);
        int ss[4] = { s4.x, s4.y, s4.z, s4.w };
        int dd[4] = { d4.x, d4.y, d4.z, d4.w };
#pragma unroll
        for (int j = 0; j < 4; j++) {
            int slot = atomicAdd(&g_cnt[dd[j]], 1);
            if (slot < CAP)
                g_adj[(size_t)dd[j] * CAP + slot] = ss[j];
        }
    }

    for (int n = blockIdx.x * TB + t; n < N_NODES; n += gridThreads) {
        const float4* xr = reinterpret_cast<const float4*>(x + (size_t)n * IN_DIM);
        float ya[HID], ra[HID];
#pragma unroll
        for (int c = 0; c < HID; c++) { ya[c] = 0.f; ra[c] = 0.f; }
#pragma unroll 2
        for (int q = 0; q < IN_DIM / 4; q++) {
            float4 v = xr[q];
#pragma unroll
            for (int c = 0; c < HID; c++) {
                const float* wl = &sWl[c * IN_DIM + 4 * q];
                const float* wr = &sWr[c * IN_DIM + 4 * q];
                ya[c] += v.x * wl[0] + v.y * wl[1] + v.z * wl[2] + v.w * wl[3];
                ra[c] += v.x * wr[0] + v.y * wr[1] + v.z * wr[2] + v.w * wr[3];
            }
        }
        uint32_t hp[8];
#pragma unroll
        for (int i = 0; i < 8; i++) {
            __half2 h = __floats2half2_rn(ya[2*i], ya[2*i+1]);
            hp[i] = *reinterpret_cast<uint32_t*>(&h);
        }
        uint4* yo = reinterpret_cast<uint4*>(g_y1h + (size_t)n * HID);
        yo[0] = make_uint4(hp[0], hp[1], hp[2], hp[3]);
        yo[1] = make_uint4(hp[4], hp[5], hp[6], hp[7]);
        float4* ro = reinterpret_cast<float4*>(g_r1 + (size_t)n * HID);
#pragma unroll
        for (int i = 0; i < HID / 4; i++)
            ro[i] = make_float4(ra[4*i], ra[4*i+1], ra[4*i+2], ra[4*i+3]);
    }

    gridBarrier(localSense);

    // ---------------- Phase B: layer-1 aggregate + collapse (2 lanes/node) --
    // base-strided loop: trip count uniform per block -> shuffles are safe.
    {
        const int halfTB = TB / 2;
        int sub = t & 1;
        for (int base = blockIdx.x * halfTB; base < N_NODES; base += gridDim.x * halfTB) {
            int node = base + (t >> 1);
            bool valid = node < N_NODES;
            int nC = valid ? node : (N_NODES - 1);

            int degFull = g_cnt[nC];
            int deg = degFull < CAP ? degFull : CAP;
            if (!valid) deg = 0;

            const int* arow = g_adj + (size_t)nC * CAP;

            float acc[8] = {0.f,0.f,0.f,0.f,0.f,0.f,0.f,0.f};
            int i = 0;
            for (; i + 8 <= deg; i += 8) {
                int4 ia = __ldg(reinterpret_cast<const int4*>(arow + i));
                int4 ib = __ldg(reinterpret_cast<const int4*>(arow + i + 4));
                uint4 v0 = ld_y1h(ia.x, sub);
                uint4 v1 = ld_y1h(ia.y, sub);
                uint4 v2 = ld_y1h(ia.z, sub);
                uint4 v3 = ld_y1h(ia.w, sub);
                uint4 v4 = ld_y1h(ib.x, sub);
                uint4 v5 = ld_y1h(ib.y, sub);
                uint4 v6 = ld_y1h(ib.z, sub);
                uint4 v7 = ld_y1h(ib.w, sub);
                acc_h8(acc, v0); acc_h8(acc, v1); acc_h8(acc, v2); acc_h8(acc, v3);
                acc_h8(acc, v4); acc_h8(acc, v5); acc_h8(acc, v6); acc_h8(acc, v7);
            }
            if (i + 4 <= deg) {
                int4 ia = __ldg(reinterpret_cast<const int4*>(arow + i));
                uint4 v0 = ld_y1h(ia.x, sub);
                uint4 v1 = ld_y1h(ia.y, sub);
                uint4 v2 = ld_y1h(ia.z, sub);
                uint4 v3 = ld_y1h(ia.w, sub);
                acc_h8(acc, v0); acc_h8(acc, v1); acc_h8(acc, v2); acc_h8(acc, v3);
                i += 4;
            }
            for (; i < deg; i++)
                acc_h8(acc, ld_y1h(arow[i], sub));

            float inv = 1.0f / fmaxf((float)degFull, 1.0f);
            const float4* rr = reinterpret_cast<const float4*>(g_r1 + (size_t)nC * HID);
            float4 r0 = rr[2*sub + 0];
            float4 r1 = rr[2*sub + 1];
            const float4* bb = reinterpret_cast<const float4*>(sbl1);
            float4 b0 = bb[2*sub + 0], b1 = bb[2*sub + 1];
            const float4* wlp = reinterpret_cast<const float4*>(sW2fc);
            float4 wl0 = wlp[2*sub + 0], wl1 = wlp[2*sub + 1];
            const float4* wrp = reinterpret_cast<const float4*>(sWr2fc);
            float4 wr0 = wrp[2*sub + 0], wr1 = wrp[2*sub + 1];

            float rv[8] = { r0.x,r0.y,r0.z,r0.w, r1.x,r1.y,r1.z,r1.w };
            float bv[8] = { b0.x,b0.y,b0.z,b0.w, b1.x,b1.y,b1.z,b1.w };
            float wlv[8]= { wl0.x,wl0.y,wl0.z,wl0.w, wl1.x,wl1.y,wl1.z,wl1.w };
            float wrv[8]= { wr0.x,wr0.y,wr0.z,wr0.w, wr1.x,wr1.y,wr1.z,wr1.w };

            float s2p = 0.f, r2p = 0.f;
#pragma unroll
            for (int k = 0; k < 8; k++) {
                float h = fmaxf(acc[k] * inv + bv[k] + rv[k], 0.f);
                s2p += h * wlv[k];
                r2p += h * wrv[k];
            }
            s2p += __shfl_xor_sync(0xFFFFFFFFu, s2p, 1);
            r2p += __shfl_xor_sync(0xFFFFFFFFu, r2p, 1);

            if (valid && sub == 0) {
                g_s2[node]  = s2p;
                g_r2s[node] = r2p;
            }
        }
    }

    gridBarrier(localSense);

    // ---------------- Phase C: layer-2 scalar aggregate + head (4 lanes) ---
    {
        const int qTB = TB / 4;
        int sub = t & 3;
        for (int base = blockIdx.x * qTB; base < N_NODES; base += gridDim.x * qTB) {
            int node = base + (t >> 2);
            bool valid = node < N_NODES;
            int nC = valid ? node : (N_NODES - 1);

            int degFull = g_cnt[nC];
            int deg = degFull < CAP ? degFull : CAP;
            if (!valid) deg = 0;

            const int* arow = g_adj + (size_t)nC * CAP;

            float s = 0.f;
            for (int b = 4 * sub; b < deg; b += 16) {
                int4 ia = __ldg(reinterpret_cast<const int4*>(arow + b));
                if (b + 0 < deg) s += __ldg(&g_s2[ia.x]);
                if (b + 1 < deg) s += __ldg(&g_s2[ia.y]);
                if (b + 2 < deg) s += __ldg(&g_s2[ia.z]);
                if (b + 3 < deg) s += __ldg(&g_s2[ia.w]);
            }
            s += __shfl_xor_sync(0xFFFFFFFFu, s, 1);
            s += __shfl_xor_sync(0xFFFFFFFFu, s, 2);

            if (valid && sub == 0) {
                float inv = 1.0f / fmaxf((float)degFull, 1.0f);
                out[node] = s * inv + sc[0] + g_r2s[node];
                g_cnt[node] = 0;   // restore invariant for the next launch
            }
        }
    }
}

// ---------------- launch ----------------
extern "C" void kernel_launch(void* const* d_in, const int* in_sizes, int n_in,
                              void* d_out, int out_size) {
    const float* x   = (const float*)d_in[0];
    const int*   ei  = (const int*)  d_in[1];
    const float* Wl1 = (const float*)d_in[2];
    const float* bl1 = (const float*)d_in[3];
    const float* Wr1 = (const float*)d_in[4];
    const float* Wl2 = (const float*)d_in[5];
    const float* bl2 = (const float*)d_in[6];
    const float* Wr2 = (const float*)d_in[7];
    const float* Wfc = (const float*)d_in[8];
    const float* bfc = (const float*)d_in[9];
    float* out = (float*)d_out;

    // grid = maxActiveBlocks * SMs, computed once — every block resident,
    // so the in-kernel spin barrier is deadlock-free.
    static int grid = 0;
    if (grid == 0) {
        int dev = 0, sms = 0, nb = 0;
        cudaGetDevice(&dev);
        cudaDeviceGetAttribute(&sms, cudaDevAttrMultiProcessorCount, dev);
        cudaOccupancyMaxActiveBlocksPerMultiprocessor(&nb, k_fused, TB, 0);
        if (nb < 1) nb = 1;
        grid = sms * nb;
    }

    k_fused<<<grid, TB>>>(x, ei, Wl1, Wr1, Wl2, Wr2, Wfc, bl1, bl2, bfc, out);
}